// round 4
// baseline (speedup 1.0000x reference)
#include <cuda_runtime.h>
#include <cuda_bf16.h>

// Greedy masked-argmax scan, thread-per-row.
// B rows, S=25 steps, V=25 vocab. Each thread owns one row and a 32-bit
// used-mask. Step s reads matrix[row, s, 0:25] (each element read exactly
// once), does a 25-wide unrolled masked argmax with strict-> ascending-index
// scan (== jnp.argmax first-occurrence tie-break), marks winner used.
//
// Outputs stashed in smem (stride-25 STS: odd stride -> conflict-free),
// flushed coalesced. Output layout: float[2*B*S]; [0,B*S) actions-as-float,
// [B*S,2*B*S) selected scores.

#define TPB 128
#define S_LEN 25
#define V_LEN 25
#define ROW_ELEMS (S_LEN * V_LEN)  // 625

__global__ __launch_bounds__(TPB)
void greedy_argmax_tpr(const float* __restrict__ in, float* __restrict__ out, int B) {
    __shared__ float s_act[TPB * S_LEN];   // 12.8 KB
    __shared__ float s_val[TPB * S_LEN];   // 12.8 KB

    const int t = threadIdx.x;
    const long long row = (long long)blockIdx.x * TPB + t;
    // Clamp for loads (tail safety); stores are guarded exactly below.
    const long long lrow = row < (long long)B ? row : (long long)B - 1;
    const float* __restrict__ rp = in + lrow * ROW_ELEMS;

    unsigned mask = 0u;

    for (int s = 0; s < S_LEN; s++) {
        const float* __restrict__ p = rp + s * V_LEN;

        // Batch the 25 loads first: high MLP, latency overlapped across steps.
        float x[V_LEN];
        #pragma unroll
        for (int v = 0; v < V_LEN; v++) x[v] = __ldg(p + v);

        // Masked argmax, strict > ascending index == first-occurrence argmax.
        float best = -INFINITY;
        int bi = 0;
        #pragma unroll
        for (int v = 0; v < V_LEN; v++) {
            bool unused = (mask & (1u << v)) == 0u;   // LOP3 w/ immediate
            if (unused && x[v] > best) {              // FSETP.GT.AND (fma pipe)
                best = x[v];                          // predicated select
                bi = v;                               // predicated mov
            }
        }
        mask |= 1u << bi;

        s_act[t * S_LEN + s] = (float)bi;  // stride-25 (odd): conflict-free
        s_val[t * S_LEN + s] = best;
    }
    __syncthreads();

    // Coalesced writeback: block covers TPB consecutive rows => contiguous
    // TPB*25-float regions in both output halves.
    const long long blockOutBase = (long long)blockIdx.x * TPB * S_LEN;
    const long long nBS = (long long)B * S_LEN;
    #pragma unroll
    for (int i = 0; i < TPB * S_LEN; i += TPB) {
        int idx = i + t;
        long long g = blockOutBase + idx;
        if (g < nBS) {
            out[g]       = s_act[idx];
            out[nBS + g] = s_val[idx];
        }
    }
}

extern "C" void kernel_launch(void* const* d_in, const int* in_sizes, int n_in,
                              void* d_out, int out_size) {
    const float* in = (const float*)d_in[0];
    float* out = (float*)d_out;
    int B = in_sizes[0] / ROW_ELEMS;                 // 65536 for the bench shape
    int blocks = (B + TPB - 1) / TPB;
    greedy_argmax_tpr<<<blocks, TPB>>>(in, out, B);
}

// round 5
// speedup vs baseline: 1.3720x; 1.3720x over previous
#include <cuda_runtime.h>
#include <cuda_bf16.h>

// Hybrid greedy masked-argmax: coalesced smem staging + thread-per-row scan.
// B rows, S=25 steps, V=25 vocab. Block = 64 threads = 64 rows.
// Steps processed in 5 chunks of 5: per chunk the block stages the 64 rows'
// 125-float segments coalesced into smem, then each thread scans its own row
// (strict >, ascending index == jnp.argmax first-occurrence tie-break).
// Output layout: float[2*B*S]; [0,B*S) actions-as-float, [B*S,2*B*S) scores.

#define TPB 64
#define ROWS 64
#define S_LEN 25
#define V_LEN 25
#define ROW_ELEMS (S_LEN * V_LEN)      // 625
#define CSTEPS 5                        // steps per chunk
#define NCHUNK (S_LEN / CSTEPS)         // 5
#define CH_COLS (CSTEPS * V_LEN)        // 125 floats per row per chunk
#define CH_FLOATS (ROWS * CH_COLS)      // 8000

__global__ __launch_bounds__(TPB, 5)
void greedy_argmax_hybrid(const float* __restrict__ in, float* __restrict__ out, int B) {
    __shared__ float slab[CH_FLOATS];            // 32.0 KB, [row][125], stride 125 (odd)
    __shared__ float s_act[ROWS * S_LEN];        // 6.4 KB, [row][step], stride 25 (odd)
    __shared__ float s_val[ROWS * S_LEN];        // 6.4 KB

    const int t = threadIdx.x;
    const long long R0 = (long long)blockIdx.x * ROWS;
    const bool full = (R0 + ROWS <= (long long)B);

    unsigned mask = 0u;

    for (int c = 0; c < NCHUNK; c++) {
        // ---- Stage chunk: 64 rows x 125 floats, coalesced (consecutive lanes
        // read consecutive floats; row boundary every 125). ----
        if (full) {
            #pragma unroll 5
            for (int k = 0; k < CH_FLOATS / TPB; k++) {          // 125 iters
                int i = t + k * TPB;
                int r = i / CH_COLS;                              // const-div
                int j = i - r * CH_COLS;
                slab[i] = __ldg(in + (R0 + r) * ROW_ELEMS + c * CH_COLS + j);
            }
        } else {
            for (int k = 0; k < CH_FLOATS / TPB; k++) {
                int i = t + k * TPB;
                int r = i / CH_COLS;
                int j = i - r * CH_COLS;
                long long row = R0 + r;
                long long lrow = (row < (long long)B) ? row : (long long)B - 1;
                slab[i] = in[lrow * ROW_ELEMS + c * CH_COLS + j];
            }
        }
        __syncthreads();

        // ---- Thread-per-row masked argmax over this chunk's 5 steps ----
        #pragma unroll
        for (int ls = 0; ls < CSTEPS; ls++) {
            const int s = c * CSTEPS + ls;
            const float* __restrict__ p = &slab[t * CH_COLS + ls * V_LEN];
            float best = -__int_as_float(0x7f800000);   // -inf
            int bi = 0;
            #pragma unroll
            for (int v = 0; v < V_LEN; v++) {
                float x = p[v];                          // LDS, conflict-free
                bool unused = (mask & (1u << v)) == 0u;  // LOP3 -> pred
                if (unused && x > best) {                // FSETP.GT.AND
                    best = x;                            // FSEL
                    bi = v;                              // SEL
                }
            }
            mask |= 1u << bi;
            s_act[t * S_LEN + s] = (float)bi;            // stride-25: conflict-free
            s_val[t * S_LEN + s] = best;
        }
        __syncthreads();                                  // slab reused next chunk
    }

    // ---- Coalesced flush: block owns contiguous ROWS*25 region in each half ----
    const long long outBase = R0 * S_LEN;
    const long long nBS = (long long)B * S_LEN;
    #pragma unroll
    for (int k = 0; k < (ROWS * S_LEN) / TPB; k++) {      // 25 iters
        int i = t + k * TPB;
        long long g = outBase + i;
        if (g < nBS) {
            out[g]       = s_act[i];
            out[nBS + g] = s_val[i];
        }
    }
}

extern "C" void kernel_launch(void* const* d_in, const int* in_sizes, int n_in,
                              void* d_out, int out_size) {
    const float* in = (const float*)d_in[0];
    float* out = (float*)d_out;
    int B = in_sizes[0] / ROW_ELEMS;                      // 65536 on bench shape
    int blocks = (B + ROWS - 1) / ROWS;

    // Max shared-memory carveout so 5 blocks (5 x 44.8 KB) fit per SM.
    static bool attr_done = false;
    if (!attr_done) {
        cudaFuncSetAttribute(greedy_argmax_hybrid,
                             cudaFuncAttributePreferredSharedMemoryCarveout,
                             cudaSharedmemCarveoutMaxShared);
        attr_done = true;
    }
    greedy_argmax_hybrid<<<blocks, TPB>>>(in, out, B);
}

// round 6
// speedup vs baseline: 2.4549x; 1.7892x over previous
#include <cuda_runtime.h>
#include <cuda_bf16.h>

// Greedy masked-argmax, hybrid v2: coalesced staging + thread-per-row scan,
// double-buffered smem with register prefetch for latency hiding.
//
// B rows, S=25 steps, V=25 vocab. Block = 128 threads = 128 rows.
// Chunk = 1 step (128 rows x 25 floats = 12.8KB). While computing chunk c
// from smem, the next chunk's 25 LDGs are already in flight into registers.
// Strict >, ascending index == jnp.argmax first-occurrence tie-break.
// Output: float[2*B*S]; [0,B*S) actions-as-float, [B*S,2*B*S) scores.

#define TPB 128
#define ROWS 128
#define S_LEN 25
#define V_LEN 25
#define ROW_ELEMS (S_LEN * V_LEN)        // 625
#define CH_FLOATS (ROWS * V_LEN)         // 3200 floats / chunk
#define LPT (CH_FLOATS / TPB)            // 25 loads per thread per chunk

__global__ __launch_bounds__(TPB, 4)
void greedy_argmax_db(const float* __restrict__ in, float* __restrict__ out, int B) {
    __shared__ float slab[2][CH_FLOATS];     // 2 x 12.8 KB, [row][vocab] stride 25 (odd)
    __shared__ float s_val[ROWS * S_LEN];    // 12.8 KB, [row][step] stride 25 (odd)
    __shared__ float s_act[ROWS * S_LEN];    // 12.8 KB

    const int t = threadIdx.x;
    const long long R0 = (long long)blockIdx.x * ROWS;

    // Per-thread staging addresses: element i = t + k*TPB of a chunk maps to
    // gmem row r = i/25, col j = i%25, addr = (R0+r)*625 + s*25 + j.
    int rr[LPT], jj[LPT];
    #pragma unroll
    for (int k = 0; k < LPT; k++) {
        int i = t + k * TPB;
        rr[k] = i / V_LEN;
        jj[k] = i - rr[k] * V_LEN;
    }

    float pf[LPT];

    // ---- Prefetch chunk 0, store to buffer 0 ----
    #pragma unroll
    for (int k = 0; k < LPT; k++) {
        long long row = R0 + rr[k];
        long long lrow = (row < (long long)B) ? row : (long long)B - 1;
        pf[k] = __ldg(in + lrow * ROW_ELEMS + 0 * V_LEN + jj[k]);
    }
    #pragma unroll
    for (int k = 0; k < LPT; k++) slab[0][t + k * TPB] = pf[k];

    unsigned mask = 0u;
    const long long lmyrow = (R0 + t < (long long)B) ? (R0 + t) : (long long)B - 1;
    (void)lmyrow;

    #pragma unroll 1
    for (int c = 0; c < S_LEN; c++) {
        __syncthreads();                          // slab[c&1] ready for all

        // Issue next chunk's loads immediately (latency hides under compute).
        if (c + 1 < S_LEN) {
            #pragma unroll
            for (int k = 0; k < LPT; k++) {
                long long row = R0 + rr[k];
                long long lrow = (row < (long long)B) ? row : (long long)B - 1;
                pf[k] = __ldg(in + lrow * ROW_ELEMS + (long long)(c + 1) * V_LEN + jj[k]);
            }
        }

        // Thread-per-row masked argmax on chunk c (from smem, conflict-free).
        {
            const float* __restrict__ p = &slab[c & 1][t * V_LEN];
            float best = -__int_as_float(0x7f800000);   // -inf
            int bi = 0;
            #pragma unroll
            for (int v = 0; v < V_LEN; v++) {
                float x = p[v];                          // LDS
                bool unused = (mask & (1u << v)) == 0u;  // LOP3 -> pred
                if (unused && x > best) { best = x; bi = v; }
            }
            mask |= 1u << bi;
            s_act[t * S_LEN + c] = (float)bi;            // stride-25: conflict-free
            s_val[t * S_LEN + c] = best;
        }

        // Commit prefetched chunk c+1 (waits on LDG scoreboard here).
        if (c + 1 < S_LEN) {
            #pragma unroll
            for (int k = 0; k < LPT; k++) slab[(c + 1) & 1][t + k * TPB] = pf[k];
        }
    }
    __syncthreads();

    // ---- Coalesced flush: block owns contiguous ROWS*25 span in each half ----
    const long long outBase = R0 * S_LEN;
    const long long nBS = (long long)B * S_LEN;
    #pragma unroll
    for (int k = 0; k < (ROWS * S_LEN) / TPB; k++) {     // 25 iters
        int i = t + k * TPB;
        long long g = outBase + i;
        if (g < nBS) {
            out[g]       = s_act[i];
            out[nBS + g] = s_val[i];
        }
    }
}

extern "C" void kernel_launch(void* const* d_in, const int* in_sizes, int n_in,
                              void* d_out, int out_size) {
    const float* in = (const float*)d_in[0];
    float* out = (float*)d_out;
    int B = in_sizes[0] / ROW_ELEMS;                     // 65536 on bench shape
    int blocks = (B + ROWS - 1) / ROWS;

    static bool attr_done = false;
    if (!attr_done) {
        cudaFuncSetAttribute(greedy_argmax_db,
                             cudaFuncAttributePreferredSharedMemoryCarveout,
                             cudaSharedmemCarveoutMaxShared);
        attr_done = true;
    }
    greedy_argmax_db<<<blocks, TPB>>>(in, out, B);
}

// round 7
// speedup vs baseline: 2.6160x; 1.0656x over previous
#include <cuda_runtime.h>
#include <cuda_bf16.h>

// Greedy masked-argmax, thread-per-row v3.
// TPB = 125 = ROWS per block (multiple of V=25 -> static staging geometry:
// element i = t + 125k  ->  row = t/25 + 5k, col = t%25, so all gmem/smem
// staging addresses are one base register + compile-time immediates).
//
// Pipeline per chunk (1 step): bar -> issue LDG(c+1)->pf regs -> compute(c)
// from smem -> commit pf -> next. Double-buffered slab, padded row stride 28
// words so each thread's slab row is 16B-aligned (LDS.128, conflict-free).
//
// Argmax: 5 independent sub-chains of 5 + ordered merge; strict '>' ascending
// == jnp.argmax first-occurrence tie-break. used = 32-bit mask.
// Output: float[2*B*S]; [0,B*S) actions-as-float, [B*S,2*B*S) scores.

#define TPB 125
#define ROWS 125
#define S_LEN 25
#define V_LEN 25
#define ROW_ELEMS 625
#define PAD 28                    // padded smem row stride (words); 112B = 7*16
#define SLAB_W (ROWS * PAD)       // 3500 words per buffer

__global__ __launch_bounds__(TPB)
void greedy_argmax_v3(const float* __restrict__ in, float* __restrict__ out, int B) {
    __shared__ __align__(16) float slab[2][SLAB_W];   // 2 x 14 KB
    __shared__ float s_val[ROWS * S_LEN];             // 12.5 KB, stride 25 (odd)
    __shared__ unsigned char s_act[ROWS * S_LEN];     // 3.1 KB

    const int t = threadIdx.x;
    const long long R0 = (long long)blockIdx.x * ROWS;
    const bool fast = (R0 + ROWS) <= (long long)B;

    const int r0 = t / V_LEN;           // 0..4
    const int j0 = t - r0 * V_LEN;      // 0..24
    // staging smem base (words): row (r0+5k) stride PAD, col j0  -> +140*k
    const int sbase = r0 * PAD + j0;
    // staging gmem base: row (R0 + r0 + 5k), col j0, chunk c -> + 3125*k + 25*c
    const float* gb = in + (R0 + r0) * (long long)ROW_ELEMS + j0;

    float pf[25];

    // ---- Prefetch + commit chunk 0 ----
    if (fast) {
        #pragma unroll
        for (int k = 0; k < 25; k++) pf[k] = __ldg(gb + 3125 * k);
    } else {
        #pragma unroll
        for (int k = 0; k < 25; k++) {
            long long row = R0 + r0 + 5 * k;
            if (row >= B) row = (long long)B - 1;
            pf[k] = __ldg(in + row * ROW_ELEMS + j0);
        }
    }
    #pragma unroll
    for (int k = 0; k < 25; k++) slab[0][sbase + 140 * k] = pf[k];

    unsigned mask = 0u;

    #pragma unroll 1
    for (int c = 0; c < S_LEN; c++) {
        __syncthreads();   // chunk c committed by all; buffer (c+1)&1 free to refill

        // ---- Issue next chunk's loads (latency overlaps compute below) ----
        if (c + 1 < S_LEN) {
            if (fast) {
                const float* g = gb + (c + 1) * V_LEN;
                #pragma unroll
                for (int k = 0; k < 25; k++) pf[k] = __ldg(g + 3125 * k);
            } else {
                #pragma unroll
                for (int k = 0; k < 25; k++) {
                    long long row = R0 + r0 + 5 * k;
                    if (row >= B) row = (long long)B - 1;
                    pf[k] = __ldg(in + row * ROW_ELEMS + (c + 1) * V_LEN + j0);
                }
            }
        }

        // ---- Compute chunk c: masked argmax over 25 (ILP-5 chains) ----
        {
            const float* __restrict__ prow = &slab[c & 1][t * PAD];
            float x[25];
            const float4* p4 = reinterpret_cast<const float4*>(prow);
            #pragma unroll
            for (int q = 0; q < 6; q++) {               // 24 values, LDS.128
                float4 v4 = p4[q];
                x[4*q+0] = v4.x; x[4*q+1] = v4.y; x[4*q+2] = v4.z; x[4*q+3] = v4.w;
            }
            x[24] = prow[24];

            const float NEGINF = -__int_as_float(0x7f800000);
            float bv0 = NEGINF, bv1 = NEGINF, bv2 = NEGINF, bv3 = NEGINF, bv4 = NEGINF;
            int   bi0 = 0, bi1 = 5, bi2 = 10, bi3 = 15, bi4 = 20;
            #pragma unroll
            for (int e = 0; e < 5; e++) {
                {int v=e;    if (!(mask&(1u<<v)) && x[v] > bv0) { bv0 = x[v]; bi0 = v; }}
                {int v=5+e;  if (!(mask&(1u<<v)) && x[v] > bv1) { bv1 = x[v]; bi1 = v; }}
                {int v=10+e; if (!(mask&(1u<<v)) && x[v] > bv2) { bv2 = x[v]; bi2 = v; }}
                {int v=15+e; if (!(mask&(1u<<v)) && x[v] > bv3) { bv3 = x[v]; bi3 = v; }}
                {int v=20+e; if (!(mask&(1u<<v)) && x[v] > bv4) { bv4 = x[v]; bi4 = v; }}
            }
            // Ordered merge: strict > keeps earlier (lower-index) chain on ties.
            float best = bv0; int bi = bi0;
            if (bv1 > best) { best = bv1; bi = bi1; }
            if (bv2 > best) { best = bv2; bi = bi2; }
            if (bv3 > best) { best = bv3; bi = bi3; }
            if (bv4 > best) { best = bv4; bi = bi4; }

            mask |= 1u << bi;
            s_val[t * S_LEN + c] = best;                  // stride 25: conflict-free
            s_act[t * S_LEN + c] = (unsigned char)bi;
        }

        // ---- Commit prefetched chunk c+1 (waits on LDG scoreboard here) ----
        if (c + 1 < S_LEN) {
            #pragma unroll
            for (int k = 0; k < 25; k++) slab[(c + 1) & 1][sbase + 140 * k] = pf[k];
        }
    }
    __syncthreads();

    // ---- Coalesced flush: block owns rows R0..R0+124 -> contiguous spans ----
    const long long outBase = R0 * S_LEN;
    const long long nBS = (long long)B * S_LEN;
    #pragma unroll
    for (int k = 0; k < S_LEN; k++) {                     // 25 iters of 125 threads
        int i = t + k * TPB;
        long long g = outBase + i;
        if (g < nBS) {
            out[g]       = (float)s_act[i];
            out[nBS + g] = s_val[i];
        }
    }
}

extern "C" void kernel_launch(void* const* d_in, const int* in_sizes, int n_in,
                              void* d_out, int out_size) {
    const float* in = (const float*)d_in[0];
    float* out = (float*)d_out;
    int B = in_sizes[0] / ROW_ELEMS;                      // 65536 on bench shape
    int blocks = (B + ROWS - 1) / ROWS;                   // 525

    static bool attr_done = false;
    if (!attr_done) {
        cudaFuncSetAttribute(greedy_argmax_v3,
                             cudaFuncAttributePreferredSharedMemoryCarveout,
                             cudaSharedmemCarveoutMaxShared);
        attr_done = true;
    }
    greedy_argmax_v3<<<blocks, TPB>>>(in, out, B);
}

// round 10
// speedup vs baseline: 2.8774x; 1.0999x over previous
#include <cuda_runtime.h>
#include <cuda_bf16.h>

// Greedy masked-argmax, thread-per-row v5: cp.async 4-deep smem ring.
// Identical to v4 except the pipeline-drain fix: at c>=23 the tail has no new
// commit groups, so wait_group 2 was a no-op and chunks 23/24 were read before
// arrival. Now: c<23 -> wait_group 2 (chunk c complete), c>=23 -> wait_group 0.
//
// B rows, S=25 steps, V=25 vocab. Block = 125 threads = 125 rows.
// Stage = one step-chunk [125 rows x 25 vocab], padded row stride 28 words
// (112B: 16B-aligned rows, LDS.128 conflict-free).
// Staging geometry (TPB==5*V): element i = t + 125k -> row t/25+5k, col t%25,
// so every gmem/smem staging address is one base register + immediates.
// Argmax: 5 ILP chains + ordered merge; strict '>' ascending index ==
// jnp.argmax first-occurrence tie-break.
// Output: float[2*B*S]; [0,B*S) actions-as-float, [B*S,2*B*S) scores.

#define TPB 125
#define ROWS 125
#define S_LEN 25
#define V_LEN 25
#define ROW_ELEMS 625
#define PAD 28
#define SLAB_W (ROWS * PAD)          // 3500 words per stage
#define STAGES 4
#define SMEM_WORDS (STAGES * SLAB_W + ROWS * S_LEN + (ROWS * S_LEN + 3) / 4)
#define SMEM_BYTES (SMEM_WORDS * 4)  // 71,628 B -> 3 blocks/SM

__device__ __forceinline__ void cpy4(unsigned dst_smem, const float* src) {
    asm volatile("cp.async.ca.shared.global [%0], [%1], 4;\n"
                 :: "r"(dst_smem), "l"(src) : "memory");
}
__device__ __forceinline__ void cp_commit() {
    asm volatile("cp.async.commit_group;\n" ::: "memory");
}
__device__ __forceinline__ void cp_wait2() {
    asm volatile("cp.async.wait_group 2;\n" ::: "memory");
}
__device__ __forceinline__ void cp_wait0() {
    asm volatile("cp.async.wait_group 0;\n" ::: "memory");
}

__device__ __forceinline__ void issue_chunk(
    int c, unsigned slab_base, int sb, const float* gb,
    const float* in, long long R0, int r0, int j0, int B, bool fast)
{
    unsigned dst = slab_base + (unsigned)(((c & (STAGES - 1)) * SLAB_W + sb) * 4);
    if (fast) {
        const float* g = gb + c * V_LEN;
        #pragma unroll
        for (int k = 0; k < 25; k++)
            cpy4(dst + 560u * k, g + 3125 * k);          // 140 words = 560 B
    } else {
        #pragma unroll
        for (int k = 0; k < 25; k++) {
            long long row = R0 + r0 + 5 * k;
            if (row >= B) row = (long long)B - 1;
            cpy4(dst + 560u * k, in + row * ROW_ELEMS + c * V_LEN + j0);
        }
    }
    cp_commit();
}

__global__ __launch_bounds__(TPB)
void greedy_argmax_v5(const float* __restrict__ in, float* __restrict__ out, int B) {
    extern __shared__ __align__(16) float smem[];
    float* slab = smem;                                   // STAGES * SLAB_W
    float* s_val = smem + STAGES * SLAB_W;                // ROWS*S_LEN, stride 25 (odd)
    unsigned char* s_act = (unsigned char*)(s_val + ROWS * S_LEN);

    const int t = threadIdx.x;
    const long long R0 = (long long)blockIdx.x * ROWS;
    const bool fast = (R0 + ROWS) <= (long long)B;

    const int r0 = t / V_LEN;            // 0..4
    const int j0 = t - r0 * V_LEN;       // 0..24
    const int sb = r0 * PAD + j0;        // staging word offset within a stage
    const float* gb = in + (R0 + r0) * (long long)ROW_ELEMS + j0;

    const unsigned slab_base = (unsigned)__cvta_generic_to_shared(slab);

    // ---- Prologue: stages 0..2 in flight (3 commit groups) ----
    issue_chunk(0, slab_base, sb, gb, in, R0, r0, j0, B, fast);
    issue_chunk(1, slab_base, sb, gb, in, R0, r0, j0, B, fast);
    issue_chunk(2, slab_base, sb, gb, in, R0, r0, j0, B, fast);

    unsigned mask = 0u;

    #pragma unroll 1
    for (int c = 0; c < S_LEN; c++) {
        // Drain fix: committed groups reach only chunk min(c+2,24). For
        // c>=23 there are no younger groups to leave pending — must drain all.
        if (c >= S_LEN - 2) cp_wait0(); else cp_wait2();
        __syncthreads();     // cross-thread visibility + buffer-reuse safety

        // ---- Compute chunk c: exact masked argmax, ILP-5 ----
        {
            const float* __restrict__ prow = &slab[(c & (STAGES - 1)) * SLAB_W + t * PAD];
            float x[25];
            const float4* p4 = reinterpret_cast<const float4*>(prow);
            #pragma unroll
            for (int q = 0; q < 6; q++) {                 // LDS.128, conflict-free
                float4 v4 = p4[q];
                x[4*q+0] = v4.x; x[4*q+1] = v4.y; x[4*q+2] = v4.z; x[4*q+3] = v4.w;
            }
            x[24] = prow[24];

            const float NEGINF = -__int_as_float(0x7f800000);
            float bv0 = NEGINF, bv1 = NEGINF, bv2 = NEGINF, bv3 = NEGINF, bv4 = NEGINF;
            int   bi0 = 0, bi1 = 5, bi2 = 10, bi3 = 15, bi4 = 20;
            #pragma unroll
            for (int e = 0; e < 5; e++) {
                {int v=e;    if (!(mask&(1u<<v)) && x[v] > bv0) { bv0 = x[v]; bi0 = v; }}
                {int v=5+e;  if (!(mask&(1u<<v)) && x[v] > bv1) { bv1 = x[v]; bi1 = v; }}
                {int v=10+e; if (!(mask&(1u<<v)) && x[v] > bv2) { bv2 = x[v]; bi2 = v; }}
                {int v=15+e; if (!(mask&(1u<<v)) && x[v] > bv3) { bv3 = x[v]; bi3 = v; }}
                {int v=20+e; if (!(mask&(1u<<v)) && x[v] > bv4) { bv4 = x[v]; bi4 = v; }}
            }
            // Ordered merge: strict > keeps the lower-index chain on ties.
            float best = bv0; int bi = bi0;
            if (bv1 > best) { best = bv1; bi = bi1; }
            if (bv2 > best) { best = bv2; bi = bi2; }
            if (bv3 > best) { best = bv3; bi = bi3; }
            if (bv4 > best) { best = bv4; bi = bi4; }

            mask |= 1u << bi;
            s_val[t * S_LEN + c] = best;                  // stride 25: conflict-free
            s_act[t * S_LEN + c] = (unsigned char)bi;
        }

        // ---- Refill: chunk c+3 into stage (c+3)%4 (safe: != c%4, and stage
        // (c-1)%4's readers all passed this iteration's barrier) ----
        if (c + 3 < S_LEN)
            issue_chunk(c + 3, slab_base, sb, gb, in, R0, r0, j0, B, fast);
    }
    __syncthreads();

    // ---- Coalesced flush: block owns contiguous ROWS*25 span in each half ----
    const long long outBase = R0 * S_LEN;
    const long long nBS = (long long)B * S_LEN;
    #pragma unroll
    for (int k = 0; k < S_LEN; k++) {                     // 25 iters x 125 threads
        int i = t + k * TPB;
        long long g = outBase + i;
        if (g < nBS) {
            out[g]       = (float)s_act[i];
            out[nBS + g] = s_val[i];
        }
    }
}

extern "C" void kernel_launch(void* const* d_in, const int* in_sizes, int n_in,
                              void* d_out, int out_size) {
    const float* in = (const float*)d_in[0];
    float* out = (float*)d_out;
    int B = in_sizes[0] / ROW_ELEMS;                      // 65536 on bench shape
    int blocks = (B + ROWS - 1) / ROWS;                   // 525

    static bool attr_done = false;
    if (!attr_done) {
        cudaFuncSetAttribute(greedy_argmax_v5,
                             cudaFuncAttributeMaxDynamicSharedMemorySize, SMEM_BYTES);
        cudaFuncSetAttribute(greedy_argmax_v5,
                             cudaFuncAttributePreferredSharedMemoryCarveout,
                             cudaSharedmemCarveoutMaxShared);
        attr_done = true;
    }
    greedy_argmax_v5<<<blocks, TPB, SMEM_BYTES>>>(in, out, B);
}

// round 12
// speedup vs baseline: 3.2562x; 1.1316x over previous
#include <cuda_runtime.h>
#include <cuda_bf16.h>

// Greedy masked-argmax, quad-per-row (P=4) v6.
// B rows, S=25 steps, V=25 vocab. Block = 256 threads = 64 rows; each row is
// owned by a 4-lane quad; lane q scans segment {[0,6),[6,13),[13,19),[19,25)}.
// 8192 warps total (~8/SMSP at 4 blocks/SM) — fixes the 3.5-warp/SMSP cap that
// latency-killed the thread-per-row family, while keeping ~6 issue slots per
// row-step (vs 10 for warp-per-row R1).
//
// Staging: proven v5 cp.async 4-deep ring (incl. tail drain fix), stage =
// 64 rows x 25 vocab, padded row stride 28 words. Scan LDS is conflict-free:
// bank = (28*rl + base_q + e) mod 32; bases {0,6,13,19} distinct mod 4 and
// 28*rl distinct mod 32 for 8 in-warp rows => injective for every e.
// Per-lane 'keep' mask folds segment length + range into the used test, so all
// lanes run one uniform unrolled 7-scan (no divergence).
//
// Merge (EXACT, first-occurrence):
//   m    = bfly-max(bv, xor 1, xor 2)          (exact float compare)
//   cand = bfly-min((bv==m) ? bi : 32)         (lowest index achieving max)
// Output: float[2*B*S]; [0,B*S) actions-as-float, [B*S,2*B*S) scores.

#define TPB 256
#define ROWSPB 64
#define S_LEN 25
#define V_LEN 25
#define ROW_ELEMS 625
#define PAD 28
#define STAGE_W (ROWSPB * PAD)      // 1792 words / stage
#define STAGES 4
#define CH_WORDS (ROWSPB * V_LEN)   // 1600 words / chunk

__device__ __forceinline__ void cpy4(unsigned dst, const float* src) {
    asm volatile("cp.async.ca.shared.global [%0], [%1], 4;\n"
                 :: "r"(dst), "l"(src) : "memory");
}
__device__ __forceinline__ void cp_commit() {
    asm volatile("cp.async.commit_group;\n" ::: "memory");
}
__device__ __forceinline__ void cp_wait2() {
    asm volatile("cp.async.wait_group 2;\n" ::: "memory");
}
__device__ __forceinline__ void cp_wait0() {
    asm volatile("cp.async.wait_group 0;\n" ::: "memory");
}

__global__ __launch_bounds__(TPB, 4)
void greedy_argmax_quad(const float* __restrict__ in, float* __restrict__ out, int B) {
    __shared__ __align__(16) float slab[STAGES * STAGE_W];   // 28,672 B
    __shared__ float s_val[ROWSPB * S_LEN];                  // 6,400 B (stride 25, odd)
    __shared__ unsigned char s_act[ROWSPB * S_LEN];          // 1,600 B

    const int t = threadIdx.x;
    const long long R0 = (long long)blockIdx.x * ROWSPB;
    const bool fast = (R0 + ROWSPB) <= (long long)B;

    // ---- Staging map: element e = t + 256k of a chunk -> (row e/25, col e%25) ----
    int sOff[7], gOff[7];
    #pragma unroll
    for (int k = 0; k < 7; k++) {
        int e = t + 256 * k;
        int r = e / V_LEN;
        int j = e - r * V_LEN;
        sOff[k] = r * PAD + j;          // word offset within a stage
        gOff[k] = r * ROW_ELEMS + j;    // word offset from chunk gmem base
    }
    const unsigned slab_base = (unsigned)__cvta_generic_to_shared(slab);
    const float* gB = in + R0 * ROW_ELEMS;   // + c*25 + gOff[k]

    // ---- Quad geometry ----
    const int rl = t >> 2;              // row within block (0..63)
    const int q  = t & 3;               // segment id
    const int base = (q == 0) ? 0 : (q == 1) ? 6 : (q == 2) ? 13 : 19;
    const int len  = (q == 1) ? 7 : 6;
    const unsigned keep = ((1u << len) - 1u) << base;  // bits of MY segment

    // ---- Issue helper (inlined twice) ----
    auto issue = [&](int c) {
        unsigned dst = slab_base + (unsigned)(((c & (STAGES - 1)) * STAGE_W) * 4);
        if (fast) {
            const float* g = gB + c * V_LEN;
            #pragma unroll
            for (int k = 0; k < 7; k++)
                if (k < 6 || t < CH_WORDS - 6 * 256)
                    cpy4(dst + (unsigned)sOff[k] * 4u, g + gOff[k]);
        } else {
            #pragma unroll
            for (int k = 0; k < 7; k++) {
                int e = t + 256 * k;
                if (e < CH_WORDS) {
                    int r = e / V_LEN;
                    int j = e - r * V_LEN;
                    long long row = R0 + r;
                    if (row >= B) row = (long long)B - 1;
                    cpy4(dst + (unsigned)(r * PAD + j) * 4u,
                         in + row * ROW_ELEMS + c * V_LEN + j);
                }
            }
        }
        cp_commit();
    };

    // ---- Prologue: 3 chunks in flight ----
    issue(0); issue(1); issue(2);

    unsigned mask = 0u;
    const float NEGINF = -__int_as_float(0x7f800000);

    #pragma unroll 1
    for (int c = 0; c < S_LEN; c++) {
        // Drain fix: committed groups reach only chunk min(c+2,24).
        if (c >= S_LEN - 2) cp_wait0(); else cp_wait2();
        __syncthreads();

        // ---- Scan my segment (uniform unrolled 7; keep-mask excludes extras) ----
        const float* __restrict__ pp =
            &slab[(c & (STAGES - 1)) * STAGE_W + rl * PAD + base];
        const unsigned mshift = (mask | ~keep) >> base;   // bit e == my elem base+e

        float bv = NEGINF;
        int be = 0;
        #pragma unroll
        for (int e = 0; e < 7; e++) {
            float x = pp[e];                               // LDS, conflict-free
            if (!((mshift >> e) & 1u) && x > bv) { bv = x; be = e; }
        }
        int bi = base + be;

        // ---- Exact quad merge (first-occurrence tie-break) ----
        float m = bv;
        m = fmaxf(m, __shfl_xor_sync(0xFFFFFFFFu, m, 1));
        m = fmaxf(m, __shfl_xor_sync(0xFFFFFFFFu, m, 2));
        int cand = (bv == m) ? bi : 32;
        cand = min(cand, __shfl_xor_sync(0xFFFFFFFFu, cand, 1));
        cand = min(cand, __shfl_xor_sync(0xFFFFFFFFu, cand, 2));

        mask |= 1u << cand;
        if (q == 0) {                                      // 8 lanes/warp, stride 25: no conflicts
            s_val[rl * S_LEN + c] = m;
            s_act[rl * S_LEN + c] = (unsigned char)cand;
        }

        // ---- Refill stage (c+3)&3 (safe: last readers passed this iter's bar) ----
        if (c + 3 < S_LEN) issue(c + 3);
    }
    __syncthreads();

    // ---- Coalesced flush: block owns rows R0..R0+63 -> contiguous spans ----
    const long long outBase = R0 * S_LEN;
    const long long nBS = (long long)B * S_LEN;
    #pragma unroll
    for (int k = 0; k < 7; k++) {
        int i = t + 256 * k;
        if (i < ROWSPB * S_LEN) {
            long long g = outBase + i;
            if (g < nBS) {
                out[g]       = (float)s_act[i];
                out[nBS + g] = s_val[i];
            }
        }
    }
}

extern "C" void kernel_launch(void* const* d_in, const int* in_sizes, int n_in,
                              void* d_out, int out_size) {
    const float* in = (const float*)d_in[0];
    float* out = (float*)d_out;
    int B = in_sizes[0] / ROW_ELEMS;                       // 65536 on bench shape
    int blocks = (B + ROWSPB - 1) / ROWSPB;                // 1024

    static bool attr_done = false;
    if (!attr_done) {
        cudaFuncSetAttribute(greedy_argmax_quad,
                             cudaFuncAttributePreferredSharedMemoryCarveout,
                             cudaSharedmemCarveoutMaxShared);
        attr_done = true;
    }
    greedy_argmax_quad<<<blocks, TPB>>>(in, out, B);
}

// round 13
// speedup vs baseline: 3.4513x; 1.0599x over previous
#include <cuda_runtime.h>
#include <cuda_bf16.h>

// Greedy masked-argmax, warp-autonomous quad-per-row v7.
// Block = 256 thr = 8 warps; each WARP owns 8 rows and is fully self-contained:
// it cp.async-stages its own 8x25 chunk into a private 4-stage smem ring and
// consumes it with only wait_group + __syncwarp — NO block barriers in the
// loop (v6's 25 __syncthreads were coupling all warps to the slowest).
//
// Row = 4-lane quad; lane q scans segment {[0,6),[6,13),[13,19),[19,25)}
// uniformly (7-iter, keep-mask folds segment bounds into the used test).
// LDS conflict-free: bank = (28*row + base_q + e) mod 32; 28*row distinct
// mod 32 (8 rows), base {0,6,13,19} distinct mod 4 => injective per e.
//
// Merge = EXACT via 64-bit packed key: hi = order-preserving uint of score
// (bijective, inverted after reduce), lo = 31-idx (max => lowest index ==
// first-occurrence; segments are index-ordered, in-lane scan first-occ).
// 2 bfly rounds (xor 1, xor 2) of paired SHFLs — half v6's serial chain.
// Full-warp shfl masks double as warp sync points => ring reuse is race-free.
//
// Ring discipline (proven in v5): 3 chunks in flight; per step wait_group 2
// (chunk c complete), tail c>=23 waits 0 (drain — no younger groups exist).
// Output: float[2*B*S]; [0,B*S) actions-as-float, [B*S,2*B*S) scores.

#define TPB 256
#define WARPS 8
#define ROWSPW 8
#define ROWSPB 64
#define S_LEN 25
#define V_LEN 25
#define ROW_ELEMS 625
#define PAD 28
#define STAGE_W (ROWSPW * PAD)        // 224 words per warp-stage
#define STAGES 4
#define WSLAB (STAGES * STAGE_W)      // 896 words per warp
#define CHW (ROWSPW * V_LEN)          // 200 words per warp-chunk

__device__ __forceinline__ void cpy4(unsigned dst, const float* src) {
    asm volatile("cp.async.ca.shared.global [%0], [%1], 4;\n"
                 :: "r"(dst), "l"(src) : "memory");
}
__device__ __forceinline__ void cp_commit() {
    asm volatile("cp.async.commit_group;\n" ::: "memory");
}
__device__ __forceinline__ void cp_wait2() {
    asm volatile("cp.async.wait_group 2;\n" ::: "memory");
}
__device__ __forceinline__ void cp_wait0() {
    asm volatile("cp.async.wait_group 0;\n" ::: "memory");
}

__global__ __launch_bounds__(TPB)
void greedy_argmax_v7(const float* __restrict__ in, float* __restrict__ out, int B) {
    __shared__ __align__(16) float slab[WARPS * WSLAB];      // 28,672 B
    __shared__ float s_val[ROWSPB * S_LEN];                  // 6,400 B (stride 25)
    __shared__ unsigned char s_act[ROWSPB * S_LEN];          // 1,600 B

    const int t = threadIdx.x;
    const int w = t >> 5;
    const int l = t & 31;
    const long long R0 = (long long)blockIdx.x * ROWSPB + (long long)w * ROWSPW;
    const bool fast = (R0 + ROWSPW) <= (long long)B;

    // ---- Per-lane staging map: element e = l + 32k -> (row e/25, col e%25) ----
    int sOff[7], gOff[7];
    #pragma unroll
    for (int k = 0; k < 7; k++) {
        int e = l + 32 * k;             // k==6 valid only for l<8 (e<200)
        int r = e / V_LEN;
        int j = e - r * V_LEN;
        sOff[k] = r * PAD + j;
        gOff[k] = r * ROW_ELEMS + j;
    }
    const unsigned wslab_base =
        (unsigned)__cvta_generic_to_shared(&slab[w * WSLAB]);
    const float* gB = in + R0 * ROW_ELEMS;

    auto issue = [&](int c) {
        unsigned dst = wslab_base + (unsigned)((c & (STAGES - 1)) * STAGE_W * 4);
        if (fast) {
            const float* g = gB + c * V_LEN;
            #pragma unroll
            for (int k = 0; k < 7; k++)
                if (k < 6 || l < CHW - 6 * 32)
                    cpy4(dst + (unsigned)sOff[k] * 4u, g + gOff[k]);
        } else {
            #pragma unroll
            for (int k = 0; k < 7; k++) {
                int e = l + 32 * k;
                if (e < CHW) {
                    int r = e / V_LEN;
                    int j = e - r * V_LEN;
                    long long row = R0 + r;
                    if (row >= B) row = (long long)B - 1;
                    cpy4(dst + (unsigned)(r * PAD + j) * 4u,
                         in + row * ROW_ELEMS + c * V_LEN + j);
                }
            }
        }
        cp_commit();
    };

    // ---- Quad geometry ----
    const int rrow = l >> 2;             // row within warp (0..7)
    const int q = l & 3;
    const int base = (q == 0) ? 0 : (q == 1) ? 6 : (q == 2) ? 13 : 19;
    const int len  = (q == 1) ? 7 : 6;
    const unsigned keep = ((1u << len) - 1u) << base;
    const int rl = w * ROWSPW + rrow;    // row within block

    // ---- Prologue: 3 chunks in flight ----
    issue(0); issue(1); issue(2);

    unsigned mask = 0u;
    const float NEGINF = -__int_as_float(0x7f800000);

    #pragma unroll 1
    for (int c = 0; c < S_LEN; c++) {
        if (c >= S_LEN - 2) cp_wait0(); else cp_wait2();
        __syncwarp();                    // warp-local visibility of staged chunk

        // ---- Scan my segment (uniform 7-iter; keep folds bounds into mask) ----
        const float* __restrict__ pp =
            &slab[w * WSLAB + (c & (STAGES - 1)) * STAGE_W + rrow * PAD + base];
        const unsigned mshift = (mask | ~keep) >> base;

        float bv = NEGINF;
        int be = 0;
        #pragma unroll
        for (int e = 0; e < 7; e++) {
            float x = pp[e];                               // LDS, conflict-free
            if (!((mshift >> e) & 1u) && x > bv) { bv = x; be = e; }
        }
        int bi = base + be;

        // ---- Exact packed-key quad merge (2 bfly rounds) ----
        unsigned b = __float_as_uint(bv);
        unsigned key = (b & 0x80000000u) ? ~b : (b | 0x80000000u);
        unsigned long long pk =
            ((unsigned long long)key << 32) | (unsigned)(31 - bi);
        {
            unsigned long long o = __shfl_xor_sync(0xFFFFFFFFu, pk, 1);
            if (o > pk) pk = o;
            o = __shfl_xor_sync(0xFFFFFFFFu, pk, 2);
            if (o > pk) pk = o;
        }
        int cand = 31 - (int)(pk & 63ull);
        unsigned kh = (unsigned)(pk >> 32);
        unsigned bb = (kh & 0x80000000u) ? (kh ^ 0x80000000u) : ~kh;  // exact inverse

        mask |= 1u << cand;
        if (q == 0) {                    // 8 lanes, stride 25 (odd): conflict-free
            s_val[rl * S_LEN + c] = __uint_as_float(bb);
            s_act[rl * S_LEN + c] = (unsigned char)cand;
        }

        // ---- Refill stage (c+3)&3 (safe: merge shfls synced the warp past
        // that stage's last read at step c-1) ----
        if (c + 3 < S_LEN) issue(c + 3);
    }
    __syncthreads();                     // only barrier: stash -> flush

    // ---- Coalesced flush: block owns rows of a contiguous span ----
    const long long outBase = (long long)blockIdx.x * ROWSPB * S_LEN;
    const long long nBS = (long long)B * S_LEN;
    #pragma unroll
    for (int k = 0; k < 7; k++) {
        int i = t + 256 * k;
        if (i < ROWSPB * S_LEN) {
            long long g = outBase + i;
            if (g < nBS) {
                out[g]       = (float)s_act[i];
                out[nBS + g] = s_val[i];
            }
        }
    }
}

extern "C" void kernel_launch(void* const* d_in, const int* in_sizes, int n_in,
                              void* d_out, int out_size) {
    const float* in = (const float*)d_in[0];
    float* out = (float*)d_out;
    int B = in_sizes[0] / ROW_ELEMS;                       // 65536 on bench shape
    int blocks = (B + ROWSPB - 1) / ROWSPB;                // 1024

    static bool attr_done = false;
    if (!attr_done) {
        cudaFuncSetAttribute(greedy_argmax_v7,
                             cudaFuncAttributePreferredSharedMemoryCarveout,
                             cudaSharedmemCarveoutMaxShared);
        attr_done = true;
    }
    greedy_argmax_v7<<<blocks, TPB>>>(in, out, B);
}

// round 14
// speedup vs baseline: 3.4856x; 1.0099x over previous
#include <cuda_runtime.h>
#include <cuda_bf16.h>

// Greedy masked-argmax, warp-autonomous quad-per-row v8.
// v7 + register diet for occupancy: __launch_bounds__(256,4) (64 regs ->
// 4 blocks/SM = 32 warps, was 3/24 at regs=80), packed 16+16-bit offset
// table (7 regs vs 14), peeled drain tail (no per-step wait-branch).
//
// Block = 256 thr = 8 warps; each WARP owns 8 rows, stages its own 8x25
// chunk via cp.async into a private 4-stage ring, consumes with wait_group +
// __syncwarp only (no block barriers in the loop).
// Row = 4-lane quad; lane q scans segment {[0,6),[6,13),[13,19),[19,25)}
// uniformly (7-iter; keep-mask folds bounds+used into one test).
// LDS conflict-free: bank=(28*row + base_q + e) mod 32 injective per e.
// Merge EXACT via 64-bit packed key (order-preserving uint | (31-idx));
// max => lowest index on ties == jnp.argmax first-occurrence.
// Ring: 3 chunks in flight; steps 0..22 wait_group 2, 23..24 wait_group 0.
// Output: float[2*B*S]; [0,B*S) actions-as-float, [B*S,2*B*S) scores.

#define TPB 256
#define WARPS 8
#define ROWSPW 8
#define ROWSPB 64
#define S_LEN 25
#define V_LEN 25
#define ROW_ELEMS 625
#define PAD 28
#define STAGE_W (ROWSPW * PAD)        // 224 words per warp-stage
#define STAGES 4
#define WSLAB (STAGES * STAGE_W)      // 896 words per warp
#define CHW (ROWSPW * V_LEN)          // 200 words per warp-chunk

__device__ __forceinline__ void cpy4(unsigned dst, const float* src) {
    asm volatile("cp.async.ca.shared.global [%0], [%1], 4;\n"
                 :: "r"(dst), "l"(src) : "memory");
}
__device__ __forceinline__ void cp_commit() {
    asm volatile("cp.async.commit_group;\n" ::: "memory");
}
__device__ __forceinline__ void cp_wait2() {
    asm volatile("cp.async.wait_group 2;\n" ::: "memory");
}
__device__ __forceinline__ void cp_wait0() {
    asm volatile("cp.async.wait_group 0;\n" ::: "memory");
}

__global__ __launch_bounds__(TPB, 4)
void greedy_argmax_v8(const float* __restrict__ in, float* __restrict__ out, int B) {
    __shared__ __align__(16) float slab[WARPS * WSLAB];      // 28,672 B
    __shared__ float s_val[ROWSPB * S_LEN];                  // 6,400 B (stride 25)
    __shared__ unsigned char s_act[ROWSPB * S_LEN];          // 1,600 B

    const int t = threadIdx.x;
    const int w = t >> 5;
    const int l = t & 31;
    const long long R0 = (long long)blockIdx.x * ROWSPB + (long long)w * ROWSPW;
    const bool fast = (R0 + ROWSPW) <= (long long)B;

    // ---- Packed staging map: element e = l + 32k -> gmem word (625r+j) in
    // hi16, smem word (28r+j) in lo16 (both < 2^16). 7 regs total. ----
    unsigned pOff[7];
    #pragma unroll
    for (int k = 0; k < 7; k++) {
        int e = l + 32 * k;             // k==6 valid only for l<8 (e<200)
        int r = e / V_LEN;
        int j = e - r * V_LEN;
        pOff[k] = ((unsigned)(r * ROW_ELEMS + j) << 16) | (unsigned)(r * PAD + j);
    }
    const unsigned wslab_base =
        (unsigned)__cvta_generic_to_shared(&slab[w * WSLAB]);
    const float* gB = in + R0 * ROW_ELEMS;

    auto issue = [&](int c) {
        unsigned dst = wslab_base + (unsigned)((c & (STAGES - 1)) * STAGE_W * 4);
        if (fast) {
            const float* g = gB + c * V_LEN;
            #pragma unroll
            for (int k = 0; k < 7; k++)
                if (k < 6 || l < CHW - 6 * 32)
                    cpy4(dst + (pOff[k] & 0xFFFFu) * 4u, g + (pOff[k] >> 16));
        } else {
            #pragma unroll
            for (int k = 0; k < 7; k++) {
                int e = l + 32 * k;
                if (e < CHW) {
                    int r = e / V_LEN;
                    int j = e - r * V_LEN;
                    long long row = R0 + r;
                    if (row >= B) row = (long long)B - 1;
                    cpy4(dst + (unsigned)(r * PAD + j) * 4u,
                         in + row * ROW_ELEMS + c * V_LEN + j);
                }
            }
        }
        cp_commit();
    };

    // ---- Quad geometry ----
    const int rrow = l >> 2;             // row within warp (0..7)
    const int q = l & 3;
    const int base = (q == 0) ? 0 : (q == 1) ? 6 : (q == 2) ? 13 : 19;
    const int len  = (q == 1) ? 7 : 6;
    const unsigned keep = ((1u << len) - 1u) << base;
    const int rl = w * ROWSPW + rrow;    // row within block

    unsigned mask = 0u;
    const float NEGINF = -__int_as_float(0x7f800000);

    auto compute = [&](int c) {
        const float* __restrict__ pp =
            &slab[w * WSLAB + (c & (STAGES - 1)) * STAGE_W + rrow * PAD + base];
        const unsigned mshift = (mask | ~keep) >> base;

        float bv = NEGINF;
        int be = 0;
        #pragma unroll
        for (int e = 0; e < 7; e++) {
            float x = pp[e];                               // LDS, conflict-free
            if (!((mshift >> e) & 1u) && x > bv) { bv = x; be = e; }
        }
        int bi = base + be;

        // Exact packed-key quad merge (2 bfly rounds).
        unsigned b = __float_as_uint(bv);
        unsigned key = (b & 0x80000000u) ? ~b : (b | 0x80000000u);
        unsigned long long pk =
            ((unsigned long long)key << 32) | (unsigned)(31 - bi);
        {
            unsigned long long o = __shfl_xor_sync(0xFFFFFFFFu, pk, 1);
            if (o > pk) pk = o;
            o = __shfl_xor_sync(0xFFFFFFFFu, pk, 2);
            if (o > pk) pk = o;
        }
        int cand = 31 - (int)(pk & 63ull);
        unsigned kh = (unsigned)(pk >> 32);
        unsigned bb = (kh & 0x80000000u) ? (kh ^ 0x80000000u) : ~kh;  // exact inverse

        mask |= 1u << cand;
        if (q == 0) {                    // 8 lanes, stride 25 (odd): conflict-free
            s_val[rl * S_LEN + c] = __uint_as_float(bb);
            s_act[rl * S_LEN + c] = (unsigned char)cand;
        }
    };

    // ---- Prologue: 3 chunks in flight ----
    issue(0); issue(1); issue(2);

    // ---- Main loop: chunk c complete once <=2 younger groups pending ----
    #pragma unroll 1
    for (int c = 0; c < S_LEN - 2; c++) {
        cp_wait2();
        __syncwarp();
        compute(c);
        if (c + 3 < S_LEN) issue(c + 3);   // stage (c+3)&3 reuse is safe: its
    }                                       // last reader finished step c-1
    // ---- Peeled drain tail: no younger groups exist for chunks 23,24 ----
    cp_wait0();
    __syncwarp();
    compute(S_LEN - 2);
    compute(S_LEN - 1);

    __syncthreads();                     // only block barrier: stash -> flush

    // ---- Coalesced flush: block owns a contiguous span in each half ----
    const long long outBase = (long long)blockIdx.x * ROWSPB * S_LEN;
    const long long nBS = (long long)B * S_LEN;
    #pragma unroll
    for (int k = 0; k < 7; k++) {
        int i = t + 256 * k;
        if (i < ROWSPB * S_LEN) {
            long long g = outBase + i;
            if (g < nBS) {
                out[g]       = (float)s_act[i];
                out[nBS + g] = s_val[i];
            }
        }
    }
}

extern "C" void kernel_launch(void* const* d_in, const int* in_sizes, int n_in,
                              void* d_out, int out_size) {
    const float* in = (const float*)d_in[0];
    float* out = (float*)d_out;
    int B = in_sizes[0] / ROW_ELEMS;                       // 65536 on bench shape
    int blocks = (B + ROWSPB - 1) / ROWSPB;                // 1024

    static bool attr_done = false;
    if (!attr_done) {
        cudaFuncSetAttribute(greedy_argmax_v8,
                             cudaFuncAttributePreferredSharedMemoryCarveout,
                             cudaSharedmemCarveoutMaxShared);
        attr_done = true;
    }
    greedy_argmax_v8<<<blocks, TPB>>>(in, out, B);
}